// round 15
// baseline (speedup 1.0000x reference)
#include <cuda_runtime.h>
#include <cuda_fp16.h>
#include <cstdint>
#include <math.h>

#define B_ 8
#define N_ 2048
#define E_ 512
#define F_ 256
#define L_ 2

#define ARRB 16384              // one operand array per stage: 128 rows x 128 B
#define STGB (2 * ARRB)         // stage: A, B = 32768 B
#define GSM  (2 * STGB)         // double buffered = 65536 B

static __device__ __constant__ float kLnEps = 1e-5f;

// ---------------------------------------------------------------------------
// Scratch (__device__ globals; no allocations allowed)
// ---------------------------------------------------------------------------
__device__ float  g_s  [B_ * N_ * N_];          // fp32 scores
__device__ __half g_p  [B_ * N_ * N_];          // probs (fp16)
__device__ __half g_qk [B_ * N_ * 2 * F_];      // q|k fused [m][512]
__device__ __half g_xs [B_ * N_ * E_];          // x fp16 (A of q/k)
__device__ __half g_xt [B_ * N_ * E_];          // x^T fp16 (B of ctx)
__device__ __half g_c  [B_ * N_ * E_];          // ctx fp16
__device__ float  g_c2 [B_ * N_ * E_];
__device__ float  g_x  [B_ * N_ * E_];
__device__ __half g_wqk[L_ * 2 * F_ * E_];      // [Wq;Wk] rows fused
__device__ float  g_bqk[L_ * 2 * F_];           // [bq;bk] fused
__device__ __half g_wc [L_ * E_ * E_];

// ---------------------------------------------------------------------------
// PTX helpers
// ---------------------------------------------------------------------------
__device__ __forceinline__ uint32_t smem_u32(const void* p) {
    uint32_t a;
    asm("{ .reg .u64 t; cvta.to.shared.u64 t, %1; cvt.u32.u64 %0, t; }"
        : "=r"(a) : "l"(p));
    return a;
}
__device__ __forceinline__ void cp16(uint32_t sa, const void* ga) {
    asm volatile("cp.async.ca.shared.global [%0], [%1], 16;"
                 :: "r"(sa), "l"(ga));
}
__device__ __forceinline__ void cp_commit() {
    asm volatile("cp.async.commit_group;" ::: "memory");
}
template <int NV>
__device__ __forceinline__ void cp_wait() {
    asm volatile("cp.async.wait_group %0;" :: "n"(NV) : "memory");
}
__device__ __forceinline__ uint32_t swz(uint32_t off) {   // SW128: bits[6:4]^=bits[9:7]
    return off ^ ((off >> 3) & 0x70);
}

#define LDSM4(r, a)                                                           \
    asm volatile("ldmatrix.sync.aligned.m8n8.x4.shared.b16 {%0,%1,%2,%3},[%4];" \
                 : "=r"((r)[0]), "=r"((r)[1]), "=r"((r)[2]), "=r"((r)[3])     \
                 : "r"(a))

#define MMA16(d, a, b0, b1)                                                   \
    asm volatile(                                                             \
        "mma.sync.aligned.m16n8k16.row.col.f32.f16.f16.f32 "                  \
        "{%0,%1,%2,%3},{%4,%5,%6,%7},{%8,%9},{%0,%1,%2,%3};"                  \
        : "+f"((d)[0]), "+f"((d)[1]), "+f"((d)[2]), "+f"((d)[3])              \
        : "r"((a)[0]), "r"((a)[1]), "r"((a)[2]), "r"((a)[3]),                 \
          "r"(b0), "r"(b1))

__device__ __forceinline__ float warp_max(float v) {
#pragma unroll
    for (int o = 16; o > 0; o >>= 1) v = fmaxf(v, __shfl_xor_sync(0xffffffffu, v, o));
    return v;
}
__device__ __forceinline__ float warp_sum(float v) {
#pragma unroll
    for (int o = 16; o > 0; o >>= 1) v += __shfl_xor_sync(0xffffffffu, v, o);
    return v;
}

// ---------------------------------------------------------------------------
// fp16 GEMM:  D[128x128] = A[128,K] * (B[128,K])^T  (single pass)
//   EPI: 0 = +bias, fp16 out   1 = mask+scale, fp32 out
//        2 = fp16 out          3 = fp32 out
// BK=64, double-buffered swizzled smem, SINGLE barrier per k-chunk:
//   cp_wait(cur) -> barrier -> issue next into buf^1 -> compute buf
// grid=(Ntile, Mtile, Z), 256 threads.
// ---------------------------------------------------------------------------
template <int EPI>
__global__ void __launch_bounds__(256, 2) gemm_fp16(
    const __half* __restrict__ A, int ldA, long sAz,
    const __half* __restrict__ Bm, int ldB, long sBz, int K,
    const float* __restrict__ bias, const int* __restrict__ rel, long sRz,
    float* __restrict__ outF, __half* __restrict__ outH, int ldC, long sCz)
{
    extern __shared__ char sm[];
    const uint32_t sbase = smem_u32(sm);
    const int tid = threadIdx.x, lane = tid & 31, wid = tid >> 5;
    const int z = blockIdx.z;
    const int bm = blockIdx.y * 128, bn = blockIdx.x * 128;
    A  += (size_t)z * sAz;
    Bm += (size_t)z * sBz;

    const int wm = (wid & 3) * 32, wn = (wid >> 2) * 64;

    float acc[2][8][4];
#pragma unroll
    for (int i = 0; i < 2; i++)
#pragma unroll
        for (int j = 0; j < 8; j++)
#pragma unroll
            for (int p = 0; p < 4; p++) acc[i][j][p] = 0.0f;

    const int nk = K / 64;

    // loader: thread handles one 128B row of one array (8 x 16B chunks)
    const int larr = tid >> 7;           // 0:A 1:B
    const int lrow = tid & 127;
    const __half* lsrc = larr ? Bm : A;
    const int lld = larr ? ldB : ldA;
    const int lgb = larr ? bn : bm;
    const __half* lptr = lsrc + (size_t)(lgb + lrow) * lld;
    const uint32_t lsw0 = (uint32_t)larr * ARRB;

    // ---- prologue: stage 0
#pragma unroll
    for (int q = 0; q < 8; q++)
        cp16(sbase + lsw0 + swz((uint32_t)(lrow * 128 + q * 16)), lptr + q * 8);
    cp_commit();

    int buf = 0;
    for (int kc = 0; kc < nk; kc++) {
        cp_wait<0>();          // chunk kc's loads (issued last iteration) done
        __syncthreads();       // visible CTA-wide; also fences buf^1 reuse

        if (kc + 1 < nk) {     // issue next chunk into the other buffer
            const int k0 = (kc + 1) * 64;
            const uint32_t sd = sbase + (buf ^ 1) * STGB + lsw0;
#pragma unroll
            for (int q = 0; q < 8; q++)
                cp16(sd + swz((uint32_t)(lrow * 128 + q * 16)),
                     lptr + k0 + q * 8);
            cp_commit();
        }

        const uint32_t st = sbase + buf * STGB;
#pragma unroll
        for (int ks = 0; ks < 4; ks++) {
            const int kb = ks * 32;
            uint32_t ah[2][4], bh[4][4];
#pragma unroll
            for (int mt = 0; mt < 2; mt++) {
                const uint32_t o = swz(
                    (uint32_t)((wm + mt * 16 + (lane & 15)) * 128 +
                               kb + (lane >> 4) * 16));
                LDSM4(ah[mt], st + o);
            }
            const int g = lane >> 3;
#pragma unroll
            for (int ng = 0; ng < 4; ng++) {
                const uint32_t o = swz(
                    (uint32_t)((wn + ng * 16 + ((g >> 1) << 3) + (lane & 7)) * 128 +
                               kb + (g & 1) * 16));
                LDSM4(bh[ng], st + ARRB + o);
            }
#pragma unroll
            for (int mt = 0; mt < 2; mt++)
#pragma unroll
                for (int ng = 0; ng < 4; ng++) {
                    MMA16(acc[mt][2 * ng],     ah[mt], bh[ng][0], bh[ng][1]);
                    MMA16(acc[mt][2 * ng + 1], ah[mt], bh[ng][2], bh[ng][3]);
                }
        }
        buf ^= 1;
    }

    // ---- epilogue
#pragma unroll
    for (int mt = 0; mt < 2; mt++)
#pragma unroll
        for (int nt = 0; nt < 8; nt++) {
            const int r0 = bm + wm + mt * 16 + (lane >> 2);
            const int c0 = bn + wn + nt * 8 + 2 * (lane & 3);
            float v0 = acc[mt][nt][0], v1 = acc[mt][nt][1];
            float v2 = acc[mt][nt][2], v3 = acc[mt][nt][3];
            if (EPI == 0) {
                const float b0 = bias[c0], b1 = bias[c0 + 1];
                v0 += b0; v1 += b1; v2 += b0; v3 += b1;
            }
#pragma unroll
            for (int h = 0; h < 2; h++) {
                const int row = r0 + h * 8;
                float x0 = h ? v2 : v0, x1 = h ? v3 : v1;
                const size_t base = (size_t)z * sCz + (size_t)row * ldC + c0;
                if (EPI == 1) {
                    const int2 e = *(const int2*)(rel + (size_t)z * sRz +
                                                  (size_t)row * ldC + c0);
                    float2 o;
                    o.x = (e.x == 0) ? -1e10f : x0 * 0.0625f;
                    o.y = (e.y == 0) ? -1e10f : x1 * 0.0625f;
                    *(float2*)(outF + base) = o;
                } else if (EPI == 3) {
                    float2 o; o.x = x0; o.y = x1;
                    *(float2*)(outF + base) = o;
                } else {
                    __half2 hv;
                    hv.x = __float2half_rn(x0);
                    hv.y = __float2half_rn(x1);
                    *(__half2*)(outH + base) = hv;
                }
            }
        }
}

// ---------------------------------------------------------------------------
// fp32 -> fp16 convert (vectorized by 4)
// ---------------------------------------------------------------------------
__global__ void __launch_bounds__(256) conv4h(
    const float* __restrict__ s, __half* __restrict__ h, int n4)
{
    int i = blockIdx.x * 256 + threadIdx.x;
    if (i >= n4) return;
    float4 v = ((const float4*)s)[i];
    __half2 h0, h1;
    h0.x = __float2half_rn(v.x); h0.y = __float2half_rn(v.y);
    h1.x = __float2half_rn(v.z); h1.y = __float2half_rn(v.w);
    ((__half2*)h)[2 * i]     = h0;
    ((__half2*)h)[2 * i + 1] = h1;
}

// ---------------------------------------------------------------------------
// Concatenate per-layer biases [bq;bk] -> [L][512]
// ---------------------------------------------------------------------------
__global__ void concat_bias(const float* __restrict__ bq,
                            const float* __restrict__ bk,
                            float* __restrict__ o)
{
    const int l = blockIdx.y;
    const int c = blockIdx.x * 256 + threadIdx.x;
    if (c < 2 * F_)
        o[l * 2 * F_ + c] = (c < F_) ? bq[l * F_ + c] : bk[l * F_ + c - F_];
}

// ---------------------------------------------------------------------------
// Transpose: x[z][n][d] fp32 -> xT fp16 [z][d][n]
// block (32,8), grid (E/32, N/32, B)
// ---------------------------------------------------------------------------
__global__ void __launch_bounds__(256) transpose_h(
    const float* __restrict__ x, __half* __restrict__ th)
{
    __shared__ float tile[32][33];
    const int z = blockIdx.z;
    const int d0 = blockIdx.x * 32, n0 = blockIdx.y * 32;
    const int tx = threadIdx.x, ty = threadIdx.y;
    const float* xb = x + (size_t)z * N_ * E_;
#pragma unroll
    for (int i = 0; i < 32; i += 8)
        tile[ty + i][tx] = xb[(size_t)(n0 + ty + i) * E_ + d0 + tx];
    __syncthreads();
    __half* thb = th + (size_t)z * E_ * N_;
#pragma unroll
    for (int i = 0; i < 32; i += 8)
        thb[(size_t)(d0 + ty + i) * N_ + n0 + tx] =
            __float2half_rn(tile[tx][ty + i]);
}

// ---------------------------------------------------------------------------
// Row softmax over N_ (2048) -> fp16 probs. One block per row.
// ---------------------------------------------------------------------------
__global__ void __launch_bounds__(256) softmax_h(
    const float* __restrict__ S, __half* __restrict__ P)
{
    __shared__ float red[8];
    const float4* row = reinterpret_cast<const float4*>(S + (size_t)blockIdx.x * N_);
    const int t = threadIdx.x;
    float4 v0 = row[t];
    float4 v1 = row[t + 256];

    float m = fmaxf(fmaxf(fmaxf(v0.x, v0.y), fmaxf(v0.z, v0.w)),
                    fmaxf(fmaxf(v1.x, v1.y), fmaxf(v1.z, v1.w)));
    m = warp_max(m);
    if ((t & 31) == 0) red[t >> 5] = m;
    __syncthreads();
    m = red[0];
#pragma unroll
    for (int i = 1; i < 8; i++) m = fmaxf(m, red[i]);
    __syncthreads();

    v0.x = expf(v0.x - m); v0.y = expf(v0.y - m);
    v0.z = expf(v0.z - m); v0.w = expf(v0.w - m);
    v1.x = expf(v1.x - m); v1.y = expf(v1.y - m);
    v1.z = expf(v1.z - m); v1.w = expf(v1.w - m);

    float s = warp_sum(v0.x + v0.y + v0.z + v0.w + v1.x + v1.y + v1.z + v1.w);
    if ((t & 31) == 0) red[t >> 5] = s;
    __syncthreads();
    s = red[0];
#pragma unroll
    for (int i = 1; i < 8; i++) s += red[i];
    const float inv = 1.0f / s;

    __half2* p2 = (__half2*)(P + (size_t)blockIdx.x * N_);
    float e[8] = {v0.x * inv, v0.y * inv, v0.z * inv, v0.w * inv,
                  v1.x * inv, v1.y * inv, v1.z * inv, v1.w * inv};
#pragma unroll
    for (int g = 0; g < 2; g++) {
#pragma unroll
        for (int p = 0; p < 2; p++) {
            __half2 hv;
            hv.x = __float2half_rn(e[g * 4 + p * 2]);
            hv.y = __float2half_rn(e[g * 4 + p * 2 + 1]);
            p2[g * 512 + 2 * t + p] = hv;
        }
    }
}

// ---------------------------------------------------------------------------
// out = LayerNorm(x + c2) * gamma + beta (fp32) and fp16 copy (for next GEMM).
// Rows of E_ (512). One block per row.
// ---------------------------------------------------------------------------
__global__ void __launch_bounds__(128) resid_ln(
    const float* __restrict__ x, const float* __restrict__ c2,
    const float* __restrict__ gam, const float* __restrict__ bet,
    float* __restrict__ out, __half* __restrict__ outh)
{
    __shared__ float red[4];
    const size_t base = (size_t)blockIdx.x * E_;
    const int t = threadIdx.x;
    float4 xv = *reinterpret_cast<const float4*>(x + base + (t << 2));
    float4 cv = *reinterpret_cast<const float4*>(c2 + base + (t << 2));
    float v0 = xv.x + cv.x, v1 = xv.y + cv.y, v2 = xv.z + cv.z, v3 = xv.w + cv.w;

    float s = warp_sum(v0 + v1 + v2 + v3);
    if ((t & 31) == 0) red[t >> 5] = s;
    __syncthreads();
    const float mean = (red[0] + red[1] + red[2] + red[3]) * (1.0f / E_);
    __syncthreads();

    float d0 = v0 - mean, d1 = v1 - mean, d2 = v2 - mean, d3 = v3 - mean;
    float ss = warp_sum(d0 * d0 + d1 * d1 + d2 * d2 + d3 * d3);
    if ((t & 31) == 0) red[t >> 5] = ss;
    __syncthreads();
    const float var = (red[0] + red[1] + red[2] + red[3]) * (1.0f / E_);
    const float r = rsqrtf(var + kLnEps);

    float4 gv = *reinterpret_cast<const float4*>(gam + (t << 2));
    float4 bv = *reinterpret_cast<const float4*>(bet + (t << 2));
    float4 o;
    o.x = d0 * r * gv.x + bv.x;
    o.y = d1 * r * gv.y + bv.y;
    o.z = d2 * r * gv.z + bv.z;
    o.w = d3 * r * gv.w + bv.w;
    *reinterpret_cast<float4*>(out + base + (t << 2)) = o;

    __half2 h0, h1;
    h0.x = __float2half_rn(o.x); h0.y = __float2half_rn(o.y);
    h1.x = __float2half_rn(o.z); h1.y = __float2half_rn(o.w);
    ((__half2*)(outh + base))[(t << 1)]     = h0;
    ((__half2*)(outh + base))[(t << 1) + 1] = h1;
}

// ---------------------------------------------------------------------------
// Launch
// ---------------------------------------------------------------------------
extern "C" void kernel_launch(void* const* d_in, const int* in_sizes, int n_in,
                              void* d_out, int out_size)
{
    const float* node = (const float*)d_in[0];
    const int*   rel  = (const int*)d_in[1];
    const float* Wq   = (const float*)d_in[2];
    const float* bq   = (const float*)d_in[3];
    const float* Wk   = (const float*)d_in[4];
    const float* bk   = (const float*)d_in[5];
    const float* Wc   = (const float*)d_in[6];
    const float* lng  = (const float*)d_in[7];
    const float* lnb  = (const float*)d_in[8];
    float* out = (float*)d_out;

    cudaFuncSetAttribute(gemm_fp16<0>, cudaFuncAttributeMaxDynamicSharedMemorySize, GSM);
    cudaFuncSetAttribute(gemm_fp16<1>, cudaFuncAttributeMaxDynamicSharedMemorySize, GSM);
    cudaFuncSetAttribute(gemm_fp16<2>, cudaFuncAttributeMaxDynamicSharedMemorySize, GSM);
    cudaFuncSetAttribute(gemm_fp16<3>, cudaFuncAttributeMaxDynamicSharedMemorySize, GSM);

    float *sp, *c2p, *xp, *bqkp;
    __half *pp, *qkp, *xsp, *xtp, *cp;
    __half *wqkp, *wcp;
    cudaGetSymbolAddress((void**)&sp,   g_s);
    cudaGetSymbolAddress((void**)&c2p,  g_c2);
    cudaGetSymbolAddress((void**)&xp,   g_x);
    cudaGetSymbolAddress((void**)&pp,   g_p);
    cudaGetSymbolAddress((void**)&qkp,  g_qk);
    cudaGetSymbolAddress((void**)&xsp,  g_xs);
    cudaGetSymbolAddress((void**)&xtp,  g_xt);
    cudaGetSymbolAddress((void**)&cp,   g_c);
    cudaGetSymbolAddress((void**)&wqkp, g_wqk);
    cudaGetSymbolAddress((void**)&bqkp, g_bqk);
    cudaGetSymbolAddress((void**)&wcp,  g_wc);

    // weights -> fp16; q/k fused per layer: rows [0,256)=Wq, [256,512)=Wk
    for (int l = 0; l < L_; l++) {
        conv4h<<<(F_ * E_ / 4 + 255) / 256, 256>>>(
            Wq + (size_t)l * F_ * E_, wqkp + (size_t)l * 2 * F_ * E_, F_ * E_ / 4);
        conv4h<<<(F_ * E_ / 4 + 255) / 256, 256>>>(
            Wk + (size_t)l * F_ * E_, wqkp + (size_t)l * 2 * F_ * E_ + F_ * E_,
            F_ * E_ / 4);
    }
    conv4h<<<(L_ * E_ * E_ / 4 + 255) / 256, 256>>>(Wc, wcp, L_ * E_ * E_ / 4);
    concat_bias<<<dim3(2, L_), 256>>>(bq, bk, bqkp);

    const int M = B_ * N_;
    const float* x_in = node;
    for (int l = 0; l < L_; l++) {
        float* x_out = (l == L_ - 1) ? out : xp;

        // x -> fp16 (layer 0 only: later layers get xs from resid_ln)
        if (l == 0)
            conv4h<<<(M * E_ / 4 + 255) / 256, 256>>>(x_in, xsp, M * E_ / 4);
        transpose_h<<<dim3(E_ / 32, N_ / 32, B_), dim3(32, 8)>>>(x_in, xtp);

        // [q|k] = x [Wq;Wk]^T + [bq;bk]   (one fused GEMM, N=512)
        gemm_fp16<0><<<dim3(2 * F_ / 128, M / 128, 1), 256, GSM>>>(
            xsp, E_, 0, wqkp + (size_t)l * 2 * F_ * E_, E_, 0,
            E_, bqkp + l * 2 * F_, nullptr, 0, nullptr, qkp, 2 * F_, 0);

        // scores = q k^T / 16, masked   (q = cols [0,256), k = cols [256,512))
        gemm_fp16<1><<<dim3(N_ / 128, N_ / 128, B_), 256, GSM>>>(
            qkp, 2 * F_, (long)N_ * 2 * F_,
            qkp + F_, 2 * F_, (long)N_ * 2 * F_,
            F_, nullptr, rel, (long)N_ * N_, sp, nullptr, N_, (long)N_ * N_);

        // softmax
        softmax_h<<<M, 256>>>(sp, pp);

        // ctx = P @ x
        gemm_fp16<2><<<dim3(E_ / 128, N_ / 128, B_), 256, GSM>>>(
            pp, N_, (long)N_ * N_, xtp, N_, (long)E_ * N_,
            N_, nullptr, nullptr, 0, nullptr, cp, E_, (long)N_ * E_);

        // c2 = ctx Wc^T
        gemm_fp16<3><<<dim3(E_ / 128, M / 128, 1), 256, GSM>>>(
            cp, E_, 0, wcp + (size_t)l * E_ * E_, E_, 0,
            E_, nullptr, nullptr, 0, c2p, nullptr, E_, 0);

        // x = LN(x + c2)  (fp32 + fp16 for next layer's A operand)
        resid_ln<<<M, 128>>>(x_in, c2p, lng + l * E_, lnb + l * E_, x_out, xsp);

        x_in = x_out;
    }
}

// round 17
// speedup vs baseline: 1.1370x; 1.1370x over previous
#include <cuda_runtime.h>
#include <cuda_fp16.h>
#include <cstdint>
#include <math.h>

#define B_ 8
#define N_ 2048
#define E_ 512
#define F_ 256
#define L_ 2

#define ASZ  32768              // A array: 256 rows x 128 B
#define BSZ  16384              // B array: 128 rows x 128 B
#define STGB (ASZ + BSZ)        // stage = 49152 B
#define GSM  (2 * STGB)         // double buffered = 98304 B

static __device__ __constant__ float kLnEps = 1e-5f;

// ---------------------------------------------------------------------------
// Scratch (__device__ globals; no allocations allowed)
// ---------------------------------------------------------------------------
__device__ __half g_s  [B_ * N_ * N_];          // fp16 scores
__device__ __half g_p  [B_ * N_ * N_];          // probs (fp16)
__device__ __half g_qk [B_ * N_ * 2 * F_];      // q|k fused [m][512]
__device__ __half g_xs [B_ * N_ * E_];          // x fp16 (A of q/k)
__device__ __half g_xt [B_ * N_ * E_];          // x^T fp16 (B of ctx)
__device__ __half g_c  [B_ * N_ * E_];          // ctx fp16
__device__ float  g_c2 [B_ * N_ * E_];
__device__ float  g_x  [B_ * N_ * E_];
__device__ __half g_wqk[L_ * 2 * F_ * E_];      // [Wq;Wk] rows fused
__device__ float  g_bqk[L_ * 2 * F_];           // [bq;bk] fused
__device__ __half g_wc [L_ * E_ * E_];

// ---------------------------------------------------------------------------
// PTX helpers
// ---------------------------------------------------------------------------
__device__ __forceinline__ uint32_t smem_u32(const void* p) {
    uint32_t a;
    asm("{ .reg .u64 t; cvta.to.shared.u64 t, %1; cvt.u32.u64 %0, t; }"
        : "=r"(a) : "l"(p));
    return a;
}
__device__ __forceinline__ void cp16(uint32_t sa, const void* ga) {
    asm volatile("cp.async.ca.shared.global [%0], [%1], 16;"
                 :: "r"(sa), "l"(ga));
}
__device__ __forceinline__ void cp_commit() {
    asm volatile("cp.async.commit_group;" ::: "memory");
}
template <int NV>
__device__ __forceinline__ void cp_wait() {
    asm volatile("cp.async.wait_group %0;" :: "n"(NV) : "memory");
}
__device__ __forceinline__ uint32_t swz(uint32_t off) {   // SW128
    return off ^ ((off >> 3) & 0x70);
}

#define LDSM4(r, a)                                                           \
    asm volatile("ldmatrix.sync.aligned.m8n8.x4.shared.b16 {%0,%1,%2,%3},[%4];" \
                 : "=r"((r)[0]), "=r"((r)[1]), "=r"((r)[2]), "=r"((r)[3])     \
                 : "r"(a))

#define MMA16(d, a, b0, b1)                                                   \
    asm volatile(                                                             \
        "mma.sync.aligned.m16n8k16.row.col.f32.f16.f16.f32 "                  \
        "{%0,%1,%2,%3},{%4,%5,%6,%7},{%8,%9},{%0,%1,%2,%3};"                  \
        : "+f"((d)[0]), "+f"((d)[1]), "+f"((d)[2]), "+f"((d)[3])              \
        : "r"((a)[0]), "r"((a)[1]), "r"((a)[2]), "r"((a)[3]),                 \
          "r"(b0), "r"(b1))

__device__ __forceinline__ float warp_max(float v) {
#pragma unroll
    for (int o = 16; o > 0; o >>= 1) v = fmaxf(v, __shfl_xor_sync(0xffffffffu, v, o));
    return v;
}
__device__ __forceinline__ float warp_sum(float v) {
#pragma unroll
    for (int o = 16; o > 0; o >>= 1) v += __shfl_xor_sync(0xffffffffu, v, o);
    return v;
}

// ---------------------------------------------------------------------------
// fp16 GEMM:  D[256x128] = A[256,K] * (B[128,K])^T
//   EPI: 0 = +bias, fp16 out   1 = mask+scale -> fp16 (masked = -65504)
//        2 = fp16 out          3 = fp32 out
// 512 threads, 16 warps (4x4 of 64x32 warp tiles), BK=64, double-buffered.
// grid=(Ncols/128, Mrows/256, Z)
// ---------------------------------------------------------------------------
template <int EPI>
__global__ void __launch_bounds__(512, 1) gemm_fp16(
    const __half* __restrict__ A, int ldA, long sAz,
    const __half* __restrict__ Bm, int ldB, long sBz, int K,
    const float* __restrict__ bias, const int* __restrict__ rel, long sRz,
    float* __restrict__ outF, __half* __restrict__ outH, int ldC, long sCz)
{
    extern __shared__ char sm[];
    const uint32_t sbase = smem_u32(sm);
    const int tid = threadIdx.x, lane = tid & 31, wid = tid >> 5;
    const int z = blockIdx.z;
    const int bm = blockIdx.y * 256, bn = blockIdx.x * 128;
    A  += (size_t)z * sAz;
    Bm += (size_t)z * sBz;

    const int wm = (wid & 3) * 64, wn = (wid >> 2) * 32;

    float acc[4][4][4];
#pragma unroll
    for (int i = 0; i < 4; i++)
#pragma unroll
        for (int j = 0; j < 4; j++)
#pragma unroll
            for (int p = 0; p < 4; p++) acc[i][j][p] = 0.0f;

    const int nk = K / 64;

    // loader: threads 0-255 -> A (1 row, 8 chunks); 256-511 -> B (half row, 4)
    const bool isA = tid < 256;
    const int arow = tid;                       // A row (if isA)
    const int bt   = tid - 256;
    const int brow = bt >> 1;                   // B row
    const int bq0  = (bt & 1) * 4;              // B quarter base
    const __half* lptr = isA ? (A + (size_t)(bm + arow) * ldA)
                             : (Bm + (size_t)(bn + brow) * ldB);

    // ---- prologue: stage 0
    if (isA) {
#pragma unroll
        for (int q = 0; q < 8; q++)
            cp16(sbase + swz((uint32_t)(arow * 128 + q * 16)), lptr + q * 8);
    } else {
#pragma unroll
        for (int q = 0; q < 4; q++)
            cp16(sbase + ASZ + swz((uint32_t)(brow * 128 + (bq0 + q) * 16)),
                 lptr + (bq0 + q) * 8);
    }
    cp_commit();

    int buf = 0;
    for (int kc = 0; kc < nk; kc++) {
        cp_wait<0>();
        __syncthreads();

        if (kc + 1 < nk) {
            const int k0 = (kc + 1) * 64;
            const uint32_t sd = sbase + (buf ^ 1) * STGB;
            if (isA) {
#pragma unroll
                for (int q = 0; q < 8; q++)
                    cp16(sd + swz((uint32_t)(arow * 128 + q * 16)),
                         lptr + k0 + q * 8);
            } else {
#pragma unroll
                for (int q = 0; q < 4; q++)
                    cp16(sd + ASZ +
                             swz((uint32_t)(brow * 128 + (bq0 + q) * 16)),
                         lptr + k0 + (bq0 + q) * 8);
            }
            cp_commit();
        }

        const uint32_t st = sbase + buf * STGB;
#pragma unroll
        for (int ks = 0; ks < 4; ks++) {
            const int kb = ks * 32;
            uint32_t ah[4][4], bh[2][4];
#pragma unroll
            for (int mt = 0; mt < 4; mt++) {
                const uint32_t o = swz(
                    (uint32_t)((wm + mt * 16 + (lane & 15)) * 128 +
                               kb + (lane >> 4) * 16));
                LDSM4(ah[mt], st + o);
            }
            const int g = lane >> 3;
#pragma unroll
            for (int ng = 0; ng < 2; ng++) {
                const uint32_t o = swz(
                    (uint32_t)((wn + ng * 16 + ((g >> 1) << 3) + (lane & 7)) * 128 +
                               kb + (g & 1) * 16));
                LDSM4(bh[ng], st + ASZ + o);
            }
#pragma unroll
            for (int mt = 0; mt < 4; mt++)
#pragma unroll
                for (int ng = 0; ng < 2; ng++) {
                    MMA16(acc[mt][2 * ng],     ah[mt], bh[ng][0], bh[ng][1]);
                    MMA16(acc[mt][2 * ng + 1], ah[mt], bh[ng][2], bh[ng][3]);
                }
        }
        buf ^= 1;
    }

    // ---- epilogue
#pragma unroll
    for (int mt = 0; mt < 4; mt++)
#pragma unroll
        for (int nt = 0; nt < 4; nt++) {
            const int r0 = bm + wm + mt * 16 + (lane >> 2);
            const int c0 = bn + wn + nt * 8 + 2 * (lane & 3);
            float v0 = acc[mt][nt][0], v1 = acc[mt][nt][1];
            float v2 = acc[mt][nt][2], v3 = acc[mt][nt][3];
            if (EPI == 0) {
                const float b0 = bias[c0], b1 = bias[c0 + 1];
                v0 += b0; v1 += b1; v2 += b0; v3 += b1;
            }
#pragma unroll
            for (int h = 0; h < 2; h++) {
                const int row = r0 + h * 8;
                float x0 = h ? v2 : v0, x1 = h ? v3 : v1;
                const size_t base = (size_t)z * sCz + (size_t)row * ldC + c0;
                if (EPI == 1) {
                    const int2 e = *(const int2*)(rel + (size_t)z * sRz +
                                                  (size_t)row * ldC + c0);
                    __half2 o;
                    o.x = __float2half_rn((e.x == 0) ? -65504.0f : x0 * 0.0625f);
                    o.y = __float2half_rn((e.y == 0) ? -65504.0f : x1 * 0.0625f);
                    *(__half2*)(outH + base) = o;
                } else if (EPI == 3) {
                    float2 o; o.x = x0; o.y = x1;
                    *(float2*)(outF + base) = o;
                } else {
                    __half2 hv;
                    hv.x = __float2half_rn(x0);
                    hv.y = __float2half_rn(x1);
                    *(__half2*)(outH + base) = hv;
                }
            }
        }
}

// ---------------------------------------------------------------------------
// fp32 -> fp16 convert (vectorized by 4)
// ---------------------------------------------------------------------------
__global__ void __launch_bounds__(256) conv4h(
    const float* __restrict__ s, __half* __restrict__ h, int n4)
{
    int i = blockIdx.x * 256 + threadIdx.x;
    if (i >= n4) return;
    float4 v = ((const float4*)s)[i];
    __half2 h0, h1;
    h0.x = __float2half_rn(v.x); h0.y = __float2half_rn(v.y);
    h1.x = __float2half_rn(v.z); h1.y = __float2half_rn(v.w);
    ((__half2*)h)[2 * i]     = h0;
    ((__half2*)h)[2 * i + 1] = h1;
}

// ---------------------------------------------------------------------------
// Concatenate per-layer biases [bq;bk] -> [L][512]
// ---------------------------------------------------------------------------
__global__ void concat_bias(const float* __restrict__ bq,
                            const float* __restrict__ bk,
                            float* __restrict__ o)
{
    const int l = blockIdx.y;
    const int c = blockIdx.x * 256 + threadIdx.x;
    if (c < 2 * F_)
        o[l * 2 * F_ + c] = (c < F_) ? bq[l * F_ + c] : bk[l * F_ + c - F_];
}

// ---------------------------------------------------------------------------
// Transpose: x[z][n][d] fp32 -> xT fp16 [z][d][n]
// ---------------------------------------------------------------------------
__global__ void __launch_bounds__(256) transpose_h(
    const float* __restrict__ x, __half* __restrict__ th)
{
    __shared__ float tile[32][33];
    const int z = blockIdx.z;
    const int d0 = blockIdx.x * 32, n0 = blockIdx.y * 32;
    const int tx = threadIdx.x, ty = threadIdx.y;
    const float* xb = x + (size_t)z * N_ * E_;
#pragma unroll
    for (int i = 0; i < 32; i += 8)
        tile[ty + i][tx] = xb[(size_t)(n0 + ty + i) * E_ + d0 + tx];
    __syncthreads();
    __half* thb = th + (size_t)z * E_ * N_;
#pragma unroll
    for (int i = 0; i < 32; i += 8)
        thb[(size_t)(d0 + ty + i) * N_ + n0 + tx] =
            __float2half_rn(tile[tx][ty + i]);
}

// ---------------------------------------------------------------------------
// Row softmax over N_ (2048) fp16 scores -> fp16 probs. One block per row.
// ---------------------------------------------------------------------------
__global__ void __launch_bounds__(256) softmax_h(
    const __half* __restrict__ S, __half* __restrict__ P)
{
    __shared__ float red[8];
    const int t = threadIdx.x;
    const uint4 raw = ((const uint4*)(S + (size_t)blockIdx.x * N_))[t];
    const __half2* hp = (const __half2*)&raw;
    float e[8];
#pragma unroll
    for (int i = 0; i < 4; i++) {
        float2 f = __half22float2(hp[i]);
        e[2 * i] = f.x; e[2 * i + 1] = f.y;
    }

    float m = e[0];
#pragma unroll
    for (int i = 1; i < 8; i++) m = fmaxf(m, e[i]);
    m = warp_max(m);
    if ((t & 31) == 0) red[t >> 5] = m;
    __syncthreads();
    m = red[0];
#pragma unroll
    for (int i = 1; i < 8; i++) m = fmaxf(m, red[i]);
    __syncthreads();

    float s = 0.0f;
#pragma unroll
    for (int i = 0; i < 8; i++) { e[i] = expf(e[i] - m); s += e[i]; }
    s = warp_sum(s);
    if ((t & 31) == 0) red[t >> 5] = s;
    __syncthreads();
    s = red[0];
#pragma unroll
    for (int i = 1; i < 8; i++) s += red[i];
    const float inv = 1.0f / s;

    uint4 oraw;
    __half2* op = (__half2*)&oraw;
#pragma unroll
    for (int i = 0; i < 4; i++) {
        op[i].x = __float2half_rn(e[2 * i] * inv);
        op[i].y = __float2half_rn(e[2 * i + 1] * inv);
    }
    ((uint4*)(P + (size_t)blockIdx.x * N_))[t] = oraw;
}

// ---------------------------------------------------------------------------
// out = LayerNorm(x + c2) * gamma + beta (fp32) and fp16 copy.
// ---------------------------------------------------------------------------
__global__ void __launch_bounds__(128) resid_ln(
    const float* __restrict__ x, const float* __restrict__ c2,
    const float* __restrict__ gam, const float* __restrict__ bet,
    float* __restrict__ out, __half* __restrict__ outh)
{
    __shared__ float red[4];
    const size_t base = (size_t)blockIdx.x * E_;
    const int t = threadIdx.x;
    float4 xv = *reinterpret_cast<const float4*>(x + base + (t << 2));
    float4 cv = *reinterpret_cast<const float4*>(c2 + base + (t << 2));
    float v0 = xv.x + cv.x, v1 = xv.y + cv.y, v2 = xv.z + cv.z, v3 = xv.w + cv.w;

    float s = warp_sum(v0 + v1 + v2 + v3);
    if ((t & 31) == 0) red[t >> 5] = s;
    __syncthreads();
    const float mean = (red[0] + red[1] + red[2] + red[3]) * (1.0f / E_);
    __syncthreads();

    float d0 = v0 - mean, d1 = v1 - mean, d2 = v2 - mean, d3 = v3 - mean;
    float ss = warp_sum(d0 * d0 + d1 * d1 + d2 * d2 + d3 * d3);
    if ((t & 31) == 0) red[t >> 5] = ss;
    __syncthreads();
    const float var = (red[0] + red[1] + red[2] + red[3]) * (1.0f / E_);
    const float r = rsqrtf(var + kLnEps);

    float4 gv = *reinterpret_cast<const float4*>(gam + (t << 2));
    float4 bv = *reinterpret_cast<const float4*>(bet + (t << 2));
    float4 o;
    o.x = d0 * r * gv.x + bv.x;
    o.y = d1 * r * gv.y + bv.y;
    o.z = d2 * r * gv.z + bv.z;
    o.w = d3 * r * gv.w + bv.w;
    *reinterpret_cast<float4*>(out + base + (t << 2)) = o;

    __half2 h0, h1;
    h0.x = __float2half_rn(o.x); h0.y = __float2half_rn(o.y);
    h1.x = __float2half_rn(o.z); h1.y = __float2half_rn(o.w);
    ((__half2*)(outh + base))[(t << 1)]     = h0;
    ((__half2*)(outh + base))[(t << 1) + 1] = h1;
}

// ---------------------------------------------------------------------------
// Launch
// ---------------------------------------------------------------------------
extern "C" void kernel_launch(void* const* d_in, const int* in_sizes, int n_in,
                              void* d_out, int out_size)
{
    const float* node = (const float*)d_in[0];
    const int*   rel  = (const int*)d_in[1];
    const float* Wq   = (const float*)d_in[2];
    const float* bq   = (const float*)d_in[3];
    const float* Wk   = (const float*)d_in[4];
    const float* bk   = (const float*)d_in[5];
    const float* Wc   = (const float*)d_in[6];
    const float* lng  = (const float*)d_in[7];
    const float* lnb  = (const float*)d_in[8];
    float* out = (float*)d_out;

    cudaFuncSetAttribute(gemm_fp16<0>, cudaFuncAttributeMaxDynamicSharedMemorySize, GSM);
    cudaFuncSetAttribute(gemm_fp16<1>, cudaFuncAttributeMaxDynamicSharedMemorySize, GSM);
    cudaFuncSetAttribute(gemm_fp16<2>, cudaFuncAttributeMaxDynamicSharedMemorySize, GSM);
    cudaFuncSetAttribute(gemm_fp16<3>, cudaFuncAttributeMaxDynamicSharedMemorySize, GSM);

    float *c2p, *xp, *bqkp;
    __half *sph, *pp, *qkp, *xsp, *xtp, *cp;
    __half *wqkp, *wcp;
    cudaGetSymbolAddress((void**)&sph,  g_s);
    cudaGetSymbolAddress((void**)&c2p,  g_c2);
    cudaGetSymbolAddress((void**)&xp,   g_x);
    cudaGetSymbolAddress((void**)&pp,   g_p);
    cudaGetSymbolAddress((void**)&qkp,  g_qk);
    cudaGetSymbolAddress((void**)&xsp,  g_xs);
    cudaGetSymbolAddress((void**)&xtp,  g_xt);
    cudaGetSymbolAddress((void**)&cp,   g_c);
    cudaGetSymbolAddress((void**)&wqkp, g_wqk);
    cudaGetSymbolAddress((void**)&bqkp, g_bqk);
    cudaGetSymbolAddress((void**)&wcp,  g_wc);

    // weights -> fp16; q/k fused per layer: rows [0,256)=Wq, [256,512)=Wk
    for (int l = 0; l < L_; l++) {
        conv4h<<<(F_ * E_ / 4 + 255) / 256, 256>>>(
            Wq + (size_t)l * F_ * E_, wqkp + (size_t)l * 2 * F_ * E_, F_ * E_ / 4);
        conv4h<<<(F_ * E_ / 4 + 255) / 256, 256>>>(
            Wk + (size_t)l * F_ * E_, wqkp + (size_t)l * 2 * F_ * E_ + F_ * E_,
            F_ * E_ / 4);
    }
    conv4h<<<(L_ * E_ * E_ / 4 + 255) / 256, 256>>>(Wc, wcp, L_ * E_ * E_ / 4);
    concat_bias<<<dim3(2, L_), 256>>>(bq, bk, bqkp);

    const int M = B_ * N_;
    const float* x_in = node;
    for (int l = 0; l < L_; l++) {
        float* x_out = (l == L_ - 1) ? out : xp;

        if (l == 0)
            conv4h<<<(M * E_ / 4 + 255) / 256, 256>>>(x_in, xsp, M * E_ / 4);
        transpose_h<<<dim3(E_ / 32, N_ / 32, B_), dim3(32, 8)>>>(x_in, xtp);

        // [q|k] = x [Wq;Wk]^T + [bq;bk]
        gemm_fp16<0><<<dim3(2 * F_ / 128, M / 256, 1), 512, GSM>>>(
            xsp, E_, 0, wqkp + (size_t)l * 2 * F_ * E_, E_, 0,
            E_, bqkp + l * 2 * F_, nullptr, 0, nullptr, qkp, 2 * F_, 0);

        // scores = q k^T / 16, masked -> fp16
        gemm_fp16<1><<<dim3(N_ / 128, N_ / 256, B_), 512, GSM>>>(
            qkp, 2 * F_, (long)N_ * 2 * F_,
            qkp + F_, 2 * F_, (long)N_ * 2 * F_,
            F_, nullptr, rel, (long)N_ * N_, nullptr, sph, N_, (long)N_ * N_);

        // softmax (fp16 in/out)
        softmax_h<<<M, 256>>>(sph, pp);

        // ctx = P @ x
        gemm_fp16<2><<<dim3(E_ / 128, N_ / 256, B_), 512, GSM>>>(
            pp, N_, (long)N_ * N_, xtp, N_, (long)E_ * N_,
            N_, nullptr, nullptr, 0, nullptr, cp, E_, (long)N_ * E_);

        // c2 = ctx Wc^T
        gemm_fp16<3><<<dim3(E_ / 128, M / 256, 1), 512, GSM>>>(
            cp, E_, 0, wcp + (size_t)l * E_ * E_, E_, 0,
            E_, nullptr, nullptr, 0, c2p, nullptr, E_, 0);

        // x = LN(x + c2)
        resid_ln<<<M, 128>>>(x_in, c2p, lng + l * E_, lnb + l * E_, x_out, xsp);

        x_in = x_out;
    }
}